// round 2
// baseline (speedup 1.0000x reference)
#include <cuda_runtime.h>

// MedianBlur: out = x + 0.2*(median3x3(x, zero-pad) - x)
// x: (8, 64, 256, 256) fp32 contiguous -> 512 independent 256x256 images.
// 1 warp = one 8-row x 256-col band. Each lane owns 8 columns (two float4s).
// Horizontal halo via warp shuffle; vertical halo via rolling row registers.

#define H 256
#define W 256
#define RPW 8           // output rows per warp
#define RES_SCALE 0.2f

__device__ __forceinline__ void load_row(const float* __restrict__ img,
                                         int g, int lane, float r[10]) {
    float4 a, b;
    if (g >= 0 && g < H) {
        const float4* p = reinterpret_cast<const float4*>(img + g * W);
        a = p[lane * 2];
        b = p[lane * 2 + 1];
    } else {
        a = make_float4(0.f, 0.f, 0.f, 0.f);
        b = a;
    }
    r[1] = a.x; r[2] = a.y; r[3] = a.z; r[4] = a.w;
    r[5] = b.x; r[6] = b.y; r[7] = b.z; r[8] = b.w;
    // col-1 comes from lane-1's b.w; col+8 from lane+1's a.x
    float lf = __shfl_up_sync(0xffffffffu, b.w, 1);
    float rt = __shfl_down_sync(0xffffffffu, a.x, 1);
    r[0] = (lane == 0)  ? 0.f : lf;   // global col -1 -> zero pad
    r[9] = (lane == 31) ? 0.f : rt;   // global col 256 -> zero pad
}

// exact median3 of (a,b,c)
__device__ __forceinline__ float med3(float a, float b, float c) {
    float lo = fminf(a, b), hi = fmaxf(a, b);
    return fminf(fmaxf(c, lo), hi);
}

__global__ void __launch_bounds__(256)
median_blur_kernel(const float* __restrict__ x, float* __restrict__ out) {
    const int lane = threadIdx.x & 31;
    const int wg   = blockIdx.x * (blockDim.x >> 5) + (threadIdx.x >> 5);
    const int n    = wg >> 5;          // image index (32 bands per image)
    const int band = wg & 31;

    const float* img = x   + (size_t)n * H * W;
    float*       o   = out + (size_t)n * H * W;
    const int y0 = band * RPW;

    float r0[10], r1[10], r2[10];
    load_row(img, y0 - 1, lane, r0);
    load_row(img, y0,     lane, r1);

    #pragma unroll
    for (int i = 0; i < RPW; ++i) {
        const int y = y0 + i;
        load_row(img, y + 1, lane, r2);

        // per-column vertical sort-3: (min, med, max) of the 3 rows.
        // Shared by the 3 horizontally-overlapping windows per column.
        float mn[10], md[10], mx[10];
        #pragma unroll
        for (int j = 0; j < 10; ++j) {
            float lo = fminf(r0[j], r1[j]);
            float hi = fmaxf(r0[j], r1[j]);
            mn[j] = fminf(lo, r2[j]);
            md[j] = fminf(fmaxf(r2[j], lo), hi);
            mx[j] = fmaxf(hi, r2[j]);
        }

        // median9 = med3( max of col-mins, med3 of col-meds, min of col-maxes )
        float res[8];
        #pragma unroll
        for (int j = 0; j < 8; ++j) {
            float a = fmaxf(fmaxf(mn[j], mn[j + 1]), mn[j + 2]);
            float b = med3(md[j], md[j + 1], md[j + 2]);
            float c = fminf(fminf(mx[j], mx[j + 1]), mx[j + 2]);
            float med = med3(a, b, c);
            float xc = r1[j + 1];
            res[j] = fmaf(RES_SCALE, med - xc, xc);
        }

        float4* op = reinterpret_cast<float4*>(o + y * W) + lane * 2;
        op[0] = make_float4(res[0], res[1], res[2], res[3]);
        op[1] = make_float4(res[4], res[5], res[6], res[7]);

        // roll rows (register renaming removes the copies under full unroll)
        #pragma unroll
        for (int j = 0; j < 10; ++j) { r0[j] = r1[j]; r1[j] = r2[j]; }
    }
}

extern "C" void kernel_launch(void* const* d_in, const int* in_sizes, int n_in,
                              void* d_out, int out_size) {
    const float* x = (const float*)d_in[0];
    float* out = (float*)d_out;
    // 512 images * 32 bands = 16384 warp-tasks; 8 warps/block -> 2048 blocks
    median_blur_kernel<<<2048, 256>>>(x, out);
}

// round 3
// speedup vs baseline: 1.0075x; 1.0075x over previous
#include <cuda_runtime.h>

// MedianBlur: out = x + 0.2*(median3x3(x, zero-pad) - x)
// x: (8, 64, 256, 256) fp32 -> 512 independent 256x256 images.
// 1 warp = one 8-row x 256-col band; lane owns 8 cols (two float4s).
// Horizontal halo via 2 warp shuffles/row; vertical via rolling registers.
// Row y+2 is prefetched (raw, un-shuffled) while row y is computed, so the
// ~150-op min/max network hides the LDG latency within a single warp.

#define H 256
#define W 256
#define RPW 8
#define RES_SCALE 0.2f

struct Raw { float4 a, b; };

__device__ __forceinline__ Raw load_raw(const float* __restrict__ img,
                                        int g, int lane) {
    Raw r;
    if (g >= 0 && g < H) {
        const float4* p = reinterpret_cast<const float4*>(img + g * W);
        r.a = p[lane * 2];
        r.b = p[lane * 2 + 1];
    } else {
        r.a = make_float4(0.f, 0.f, 0.f, 0.f);
        r.b = r.a;
    }
    return r;
}

// finish a row: distribute raw float4s + fetch halos from neighbor lanes
__device__ __forceinline__ void finish_row(const Raw& p, int lane, float r[10]) {
    r[1] = p.a.x; r[2] = p.a.y; r[3] = p.a.z; r[4] = p.a.w;
    r[5] = p.b.x; r[6] = p.b.y; r[7] = p.b.z; r[8] = p.b.w;
    float lf = __shfl_up_sync(0xffffffffu, p.b.w, 1);
    float rt = __shfl_down_sync(0xffffffffu, p.a.x, 1);
    r[0] = (lane == 0)  ? 0.f : lf;
    r[9] = (lane == 31) ? 0.f : rt;
}

// vertical sort-3 of one column (exact min/med/max)
__device__ __forceinline__ void sort3(float x0, float x1, float x2,
                                      float& mn, float& md, float& mx) {
    float lo = fminf(x0, x1);
    float hi = fmaxf(x0, x1);
    mn = fminf(lo, x2);
    md = fminf(fmaxf(x2, lo), hi);
    mx = fmaxf(hi, x2);
}

__device__ __forceinline__ float med3(float a, float b, float c) {
    float lo = fminf(a, b), hi = fmaxf(a, b);
    return fminf(fmaxf(c, lo), hi);
}

__global__ void __launch_bounds__(256, 4)
median_blur_kernel(const float* __restrict__ x, float* __restrict__ out) {
    const int lane = threadIdx.x & 31;
    const int wg   = blockIdx.x * (blockDim.x >> 5) + (threadIdx.x >> 5);
    const int n    = wg >> 5;          // image (32 bands per image)
    const int band = wg & 31;

    const float* img = x   + (size_t)n * H * W;
    float*       o   = out + (size_t)n * H * W;
    const int y0 = band * RPW;

    float r0[10], r1[10], r2[10];
    {
        Raw t0 = load_raw(img, y0 - 1, lane);
        Raw t1 = load_raw(img, y0,     lane);
        finish_row(t0, lane, r0);
        finish_row(t1, lane, r1);
    }
    Raw pre = load_raw(img, y0 + 1, lane);   // always in range (y0+1 <= 249)

    #pragma unroll
    for (int i = 0; i < RPW; ++i) {
        const int y = y0 + i;

        // complete row y+1 from the prefetched raw data
        finish_row(pre, lane, r2);

        // prefetch row y+2 (raw); used next iteration. OOB -> zeros.
        pre = load_raw(img, y + 2, lane);

        // sliding 3-column window merge; 9 live temps instead of 30
        float mn0, md0, mx0, mn1, md1, mx1, mn2, md2, mx2;
        sort3(r0[0], r1[0], r2[0], mn0, md0, mx0);
        sort3(r0[1], r1[1], r2[1], mn1, md1, mx1);

        float res[8];
        #pragma unroll
        for (int j = 0; j < 8; ++j) {
            sort3(r0[j + 2], r1[j + 2], r2[j + 2], mn2, md2, mx2);
            float A = fmaxf(fmaxf(mn0, mn1), mn2);
            float C = fminf(fminf(mx0, mx1), mx2);
            float B = med3(md0, md1, md2);
            float med = med3(A, B, C);
            float xc = r1[j + 1];
            res[j] = fmaf(RES_SCALE, med - xc, xc);
            mn0 = mn1; md0 = md1; mx0 = mx1;
            mn1 = mn2; md1 = md2; mx1 = mx2;
        }

        float4* op = reinterpret_cast<float4*>(o + y * W) + lane * 2;
        op[0] = make_float4(res[0], res[1], res[2], res[3]);
        op[1] = make_float4(res[4], res[5], res[6], res[7]);

        #pragma unroll
        for (int j = 0; j < 10; ++j) { r0[j] = r1[j]; r1[j] = r2[j]; }
    }
}

extern "C" void kernel_launch(void* const* d_in, const int* in_sizes, int n_in,
                              void* d_out, int out_size) {
    const float* x = (const float*)d_in[0];
    float* out = (float*)d_out;
    median_blur_kernel<<<2048, 256>>>(x, out);
}